// round 15
// baseline (speedup 1.0000x reference)
#include <cuda_runtime.h>
#include <cuda_fp16.h>
#include <math.h>
#include <stdint.h>

#define NEXP 64
#define KSEL 8
#define DDIM 1024
#define MTILE 32
#define NCHUNK 32
#define MAXBLK 1024
#define S11 2048.0f
#define I11 4.8828125e-4f
#define STEP_STRIDE 1024

__device__ float g_part[MAXBLK * NEXP];
__device__ uint32_t Bfrag[NCHUNK * 2 * 2 * 8 * 64];

__device__ __forceinline__ uint32_t h2u(half2 h) {
    return *reinterpret_cast<uint32_t*>(&h);
}
__device__ __forceinline__ void split2(float2 v, uint32_t& h, uint32_t& l) {
    half2 hh = __float22half2_rn(v);
    float2 hb = __half22float2(hh);
    half2 ll = __float22half2_rn(
        make_float2((v.x - hb.x) * S11, (v.y - hb.y) * S11));
    h = h2u(hh);
    l = h2u(ll);
}

#define MMA_F16_ACC(cc, a, b0, b1)                                             \
    asm volatile(                                                              \
        "mma.sync.aligned.m16n8k16.row.col.f32.f16.f16.f32 "                   \
        "{%0,%1,%2,%3},{%4,%5,%6,%7},{%8,%9},{%0,%1,%2,%3};"                   \
        : "+f"((cc)[0]), "+f"((cc)[1]), "+f"((cc)[2]), "+f"((cc)[3])           \
        : "r"((a)[0]), "r"((a)[1]), "r"((a)[2]), "r"((a)[3]), "r"(b0), "r"(b1))
#define MMA_F16_NEW(dd, a, b0, b1)                                             \
    asm volatile(                                                              \
        "mma.sync.aligned.m16n8k16.row.col.f32.f16.f16.f32 "                   \
        "{%0,%1,%2,%3},{%4,%5,%6,%7},{%8,%9},{%10,%11,%12,%13};"               \
        : "=f"((dd)[0]), "=f"((dd)[1]), "=f"((dd)[2]), "=f"((dd)[3])           \
        : "r"((a)[0]), "r"((a)[1]), "r"((a)[2]), "r"((a)[3]), "r"(b0), "r"(b1),\
          "f"(0.0f), "f"(0.0f), "f"(0.0f), "f"(0.0f))

__global__ void wsplit_kernel(const float* __restrict__ w)
{
    int idx = blockIdx.x * 256 + threadIdx.x;
    int n = idx >> 9;
    int kp = idx & 511;
    float2 v = *(const float2*)(w + (size_t)n * DDIM + kp * 2);
    uint32_t h, l;
    split2(v, h, l);
    int k = kp * 2;
    int ch = k >> 5, win = k & 31;
    int s = win >> 4, kk = win & 15;
    int sl = kk >> 3, q = (kk & 7) >> 1;
    int tile = n >> 3, lane = (n & 7) * 4 + q;
    uint32_t base = (uint32_t)(ch * 2 + s) * STEP_STRIDE + tile * 64 + lane * 2 + sl;
    Bfrag[base]       = h;
    Bfrag[base + 512] = l;
}

__global__ void __launch_bounds__(128, 4) gate_kernel(
    const float* __restrict__ x,
    const float* __restrict__ nw, const float* __restrict__ noise,
    float* __restrict__ out_w, float* __restrict__ out_ids)
{
    __shared__ __align__(16) float U[MTILE * 65];
    __shared__ float nw_s[NEXP];
    __shared__ float wsum0[NEXP];

    const int tid    = threadIdx.x;
    const int wid    = tid >> 5;        // 0..3
    const int lane   = tid & 31;
    const int quad   = lane & 3;
    const int r0     = lane >> 2;
    const int rowgrp = wid >> 1;        // 0..1
    const int eg     = wid & 1;
    const int base   = blockIdx.x * MTILE;

    if (tid < NEXP) nw_s[tid] = nw[tid];

    const float* pA  = x + (size_t)(base + rowgrp * 16 + r0) * DDIM + quad * 2;
    const float* pA8 = pA + 8 * DDIM;
    const uint32_t* const Bp = Bfrag + (uint32_t)(eg * 4) * 64 + lane * 2;

    float c0[4][4], c1[4][4];
#pragma unroll
    for (int t = 0; t < 4; t++)
#pragma unroll
        for (int i = 0; i < 4; i++) { c0[t][i] = 0.f; c1[t][i] = 0.f; }

#define LDA(ch, a) do {                                                        \
    _Pragma("unroll")                                                          \
    for (int _s2 = 0; _s2 < 2; _s2++) {                                        \
        *(float2*)&(a)[_s2 * 8 + 0] = *(const float2*)(pA  + (ch) * 32 + _s2 * 16);     \
        *(float2*)&(a)[_s2 * 8 + 2] = *(const float2*)(pA8 + (ch) * 32 + _s2 * 16);     \
        *(float2*)&(a)[_s2 * 8 + 4] = *(const float2*)(pA  + (ch) * 32 + _s2 * 16 + 8); \
        *(float2*)&(a)[_s2 * 8 + 6] = *(const float2*)(pA8 + (ch) * 32 + _s2 * 16 + 8); \
    }                                                                          \
} while (0)

#define CHUNK_BODY(ch, aC, aN) do {                                            \
    if ((ch) + 1 < NCHUNK) LDA((ch) + 1, aN);                                  \
    _Pragma("unroll")                                                          \
    for (int _s = 0; _s < 2; _s++) {                                           \
        uint32_t ah[4], al[4];                                                 \
        _Pragma("unroll")                                                      \
        for (int _i = 0; _i < 4; _i++)                                         \
            split2(*(float2*)&(aC)[_s * 8 + _i * 2], ah[_i], al[_i]);          \
        const uint32_t* bp = Bp + ((uint32_t)(ch) * 2 + _s) * STEP_STRIDE;     \
        float dd[4][4];                                                        \
        _Pragma("unroll")                                                      \
        for (int _t = 0; _t < 4; _t++) {                                       \
            uint2 bh = *(const uint2*)(bp + _t * 64);                          \
            MMA_F16_NEW(dd[_t], ah, bh.x, bh.y);                               \
        }                                                                      \
        _Pragma("unroll")                                                      \
        for (int _t = 0; _t < 4; _t++) {                                       \
            uint2 bl = *(const uint2*)(bp + _t * 64 + 512);                    \
            MMA_F16_ACC(c1[_t], ah, bl.x, bl.y);                               \
        }                                                                      \
        _Pragma("unroll")                                                      \
        for (int _t = 0; _t < 4; _t++) {                                       \
            uint2 bh = *(const uint2*)(bp + _t * 64);                          \
            MMA_F16_ACC(c1[_t], al, bh.x, bh.y);                               \
        }                                                                      \
        _Pragma("unroll")                                                      \
        for (int _t = 0; _t < 4; _t++) {                                       \
            c0[_t][0] += dd[_t][0]; c0[_t][1] += dd[_t][1];                    \
            c0[_t][2] += dd[_t][2]; c0[_t][3] += dd[_t][3];                    \
        }                                                                      \
    }                                                                          \
} while (0)

    float aCur[16], aNxt[16];
    LDA(0, aCur);
#pragma unroll 1
    for (int cc = 0; cc < NCHUNK; cc += 2) {
        CHUNK_BODY(cc, aCur, aNxt);
        CHUNK_BODY(cc + 1, aNxt, aCur);
    }

    {
        int rA = rowgrp * 16 + r0;
#pragma unroll
        for (int t = 0; t < 4; t++) {
            int cb = (eg * 4 + t) * 8 + 2 * quad;
#pragma unroll
            for (int i = 0; i < 4; i++) {
                float v = fmaf(c1[t][i], I11, c0[t][i]);
                int rr = rA + (i >> 1) * 8;
                U[rr * 65 + cb + (i & 1)] = v;
            }
        }
    }
    __syncthreads();

    // epilogue: warp 0, one row per lane (32 rows)
    if (tid < 32) {
        const int r = tid;
        float L[64];
#pragma unroll
        for (int e = 0; e < 64; e++) L[e] = U[r * 65 + e];

        float m = -INFINITY;
#pragma unroll
        for (int e = 0; e < 64; e++) m = fmaxf(m, L[e]);
        float s = 0.f;
#pragma unroll
        for (int e = 0; e < 64; e++) s += __expf(L[e] - m);
        float sinv = 1.f / s;

#pragma unroll
        for (int e = 0; e < 64; e++) {
            float v = __expf(L[e] - m) * sinv;
            v += __shfl_xor_sync(0xffffffffu, v, 16);
            v += __shfl_xor_sync(0xffffffffu, v, 8);
            v += __shfl_xor_sync(0xffffffffu, v, 4);
            v += __shfl_xor_sync(0xffffffffu, v, 2);
            v += __shfl_xor_sync(0xffffffffu, v, 1);
            if ((e & 31) == lane) wsum0[e] = v;
        }

        const float4* np = (const float4*)(noise + (size_t)(base + r) * NEXP);
#pragma unroll
        for (int q = 0; q < 16; q++) {
            float4 nv = np[q];
            L[q * 4 + 0] = fmaf(nv.x, nw_s[q * 4 + 0], L[q * 4 + 0]);
            L[q * 4 + 1] = fmaf(nv.y, nw_s[q * 4 + 1], L[q * 4 + 1]);
            L[q * 4 + 2] = fmaf(nv.z, nw_s[q * 4 + 2], L[q * 4 + 2]);
            L[q * 4 + 3] = fmaf(nv.w, nw_s[q * 4 + 3], L[q * 4 + 3]);
        }

        float best[KSEL];
        int bid[KSEL];
        unsigned long long used = 0ull;
#pragma unroll
        for (int k = 0; k < KSEL; k++) {
            float mv = -INFINITY;
            int mi = 0;
#pragma unroll
            for (int e = 0; e < 64; e++) {
                bool ok = !((used >> e) & 1ull);
                if (ok && L[e] > mv) { mv = L[e]; mi = e; }
            }
            used |= 1ull << mi;
            best[k] = mv;
            bid[k] = mi;
        }
        float m0 = best[0];
        float ss = 0.f;
#pragma unroll
        for (int k = 0; k < KSEL; k++) ss += __expf(best[k] - m0);
        float inv = 1.f / ss;

        float4 z = {0.f, 0.f, 0.f, 0.f};
        float4* ow = (float4*)(out_w + (size_t)(base + r) * NEXP);
#pragma unroll
        for (int q = 0; q < 16; q++) ow[q] = z;
#pragma unroll
        for (int k = 0; k < KSEL; k++) {
            out_w[(size_t)(base + r) * NEXP + bid[k]] = __expf(best[k] - m0) * inv;
            out_ids[(size_t)(base + r) * KSEL + k] = (float)bid[k];
        }
    }
    __syncthreads();
    if (tid < NEXP)
        g_part[blockIdx.x * NEXP + tid] = wsum0[tid];
}

__global__ void __launch_bounds__(1024) loss_kernel(
    int nBlocks, int N, float* __restrict__ out_loss)
{
    __shared__ double red[1024];
    const int t = threadIdx.x;
    const int e = t & 63, g = t >> 6;
    double s = 0.0;
    for (int b = g; b < nBlocks; b += 16) s += (double)g_part[b * NEXP + e];
    red[t] = s;
    __syncthreads();
    for (int off = 512; off >= 64; off >>= 1) {
        if (t < off) red[t] += red[t + off];
        __syncthreads();
    }
    if (t < 64) {
        double d = red[t] / (double)N - 1.0 / 64.0;
        red[t] = d * d;
    }
    __syncthreads();
    for (int off = 32; off >= 1; off >>= 1) {
        if (t < off) red[t] += red[t + off];
        __syncthreads();
    }
    if (t == 0) *out_loss = (float)(red[0] / 64.0 * 0.01);
}

extern "C" void kernel_launch(void* const* d_in, const int* in_sizes, int n_in,
                              void* d_out, int out_size)
{
    const float* x     = (const float*)d_in[0];  // [N, 1024]
    const float* w     = (const float*)d_in[1];  // [64, 1024]
    const float* nw    = (const float*)d_in[2];  // [64]
    const float* noise = (const float*)d_in[3];  // [N, 64]

    int N = in_sizes[3] / NEXP;
    int nBlocks = N / MTILE;   // 1024

    float* out      = (float*)d_out;
    float* out_w    = out;
    float* out_ids  = out + (size_t)N * NEXP;
    float* out_loss = out + (size_t)N * NEXP + (size_t)N * KSEL;

    wsplit_kernel<<<128, 256>>>(w);
    gate_kernel<<<nBlocks, 128>>>(x, nw, noise, out_w, out_ids);
    loss_kernel<<<1, 1024>>>(nBlocks, N, out_loss);
}

// round 16
// speedup vs baseline: 1.1604x; 1.1604x over previous
#include <cuda_runtime.h>
#include <cuda_fp16.h>
#include <math.h>
#include <stdint.h>

#define NEXP 64
#define KSEL 8
#define DDIM 1024
#define MTILE 64
#define NCHUNK 32
#define NBLK 512
#define S11 2048.0f
#define I11 4.8828125e-4f
#define STEP_STRIDE 1024

__device__ float g_part[NBLK * NEXP];
__device__ uint32_t Bfrag[NCHUNK * 2 * 2 * 8 * 64];
__device__ unsigned int g_done;

__device__ __forceinline__ uint32_t h2u(half2 h) {
    return *reinterpret_cast<uint32_t*>(&h);
}
__device__ __forceinline__ void split2(float2 v, uint32_t& h, uint32_t& l) {
    half2 hh = __float22half2_rn(v);
    float2 hb = __half22float2(hh);
    half2 ll = __float22half2_rn(
        make_float2((v.x - hb.x) * S11, (v.y - hb.y) * S11));
    h = h2u(hh);
    l = h2u(ll);
}

#define MMA_F16_ACC(cc, a, b0, b1)                                             \
    asm volatile(                                                              \
        "mma.sync.aligned.m16n8k16.row.col.f32.f16.f16.f32 "                   \
        "{%0,%1,%2,%3},{%4,%5,%6,%7},{%8,%9},{%0,%1,%2,%3};"                   \
        : "+f"((cc)[0]), "+f"((cc)[1]), "+f"((cc)[2]), "+f"((cc)[3])           \
        : "r"((a)[0]), "r"((a)[1]), "r"((a)[2]), "r"((a)[3]), "r"(b0), "r"(b1))
#define MMA_F16_NEW(dd, a, b0, b1)                                             \
    asm volatile(                                                              \
        "mma.sync.aligned.m16n8k16.row.col.f32.f16.f16.f32 "                   \
        "{%0,%1,%2,%3},{%4,%5,%6,%7},{%8,%9},{%10,%11,%12,%13};"               \
        : "=f"((dd)[0]), "=f"((dd)[1]), "=f"((dd)[2]), "=f"((dd)[3])           \
        : "r"((a)[0]), "r"((a)[1]), "r"((a)[2]), "r"((a)[3]), "r"(b0), "r"(b1),\
          "f"(0.0f), "f"(0.0f), "f"(0.0f), "f"(0.0f))

__global__ void wsplit_kernel(const float* __restrict__ w)
{
    int idx = blockIdx.x * 256 + threadIdx.x;
    int n = idx >> 9;
    int kp = idx & 511;
    float2 v = *(const float2*)(w + (size_t)n * DDIM + kp * 2);
    uint32_t h, l;
    split2(v, h, l);
    int k = kp * 2;
    int ch = k >> 5, win = k & 31;
    int s = win >> 4, kk = win & 15;
    int sl = kk >> 3, q = (kk & 7) >> 1;
    int tile = n >> 3, lane = (n & 7) * 4 + q;
    uint32_t base = (uint32_t)(ch * 2 + s) * STEP_STRIDE + tile * 64 + lane * 2 + sl;
    Bfrag[base]       = h;
    Bfrag[base + 512] = l;
}

__global__ void __launch_bounds__(256, 2) gate_kernel(
    const float* __restrict__ x,
    const float* __restrict__ nw, const float* __restrict__ noise,
    float* __restrict__ out_w, float* __restrict__ out_ids,
    float* __restrict__ out_loss, int N)
{
    __shared__ __align__(16) float U[MTILE * 65];
    __shared__ float nw_s[NEXP];
    __shared__ float wsum[4][NEXP];
    __shared__ double red[256];
    __shared__ unsigned int isLast;

    const int tid    = threadIdx.x;
    const int wid    = tid >> 5;        // 0..7
    const int lane   = tid & 31;
    const int quad   = lane & 3;
    const int r0     = lane >> 2;
    const int rowgrp = wid >> 1;        // 0..3
    const int eg     = wid & 1;
    const int base   = blockIdx.x * MTILE;

    if (tid < NEXP) nw_s[tid] = nw[tid];

    const float* pA  = x + (size_t)(base + rowgrp * 16 + r0) * DDIM + quad * 2;
    const float* pA8 = pA + 8 * DDIM;
    const uint32_t* const Bp = Bfrag + (uint32_t)(eg * 4) * 64 + lane * 2;

    float c0[4][4], c1[4][4];
#pragma unroll
    for (int t = 0; t < 4; t++)
#pragma unroll
        for (int i = 0; i < 4; i++) { c0[t][i] = 0.f; c1[t][i] = 0.f; }

#define LDA(ch, a) do {                                                        \
    _Pragma("unroll")                                                          \
    for (int _s2 = 0; _s2 < 2; _s2++) {                                        \
        *(float2*)&(a)[_s2 * 8 + 0] = *(const float2*)(pA  + (ch) * 32 + _s2 * 16);     \
        *(float2*)&(a)[_s2 * 8 + 2] = *(const float2*)(pA8 + (ch) * 32 + _s2 * 16);     \
        *(float2*)&(a)[_s2 * 8 + 4] = *(const float2*)(pA  + (ch) * 32 + _s2 * 16 + 8); \
        *(float2*)&(a)[_s2 * 8 + 6] = *(const float2*)(pA8 + (ch) * 32 + _s2 * 16 + 8); \
    }                                                                          \
} while (0)

#define CHUNK_BODY(ch, aC, aN) do {                                            \
    if ((ch) + 1 < NCHUNK) LDA((ch) + 1, aN);                                  \
    _Pragma("unroll")                                                          \
    for (int _s = 0; _s < 2; _s++) {                                           \
        uint32_t ah[4], al[4];                                                 \
        _Pragma("unroll")                                                      \
        for (int _i = 0; _i < 4; _i++)                                         \
            split2(*(float2*)&(aC)[_s * 8 + _i * 2], ah[_i], al[_i]);          \
        const uint32_t* bp = Bp + ((uint32_t)(ch) * 2 + _s) * STEP_STRIDE;     \
        float dd[4][4];                                                        \
        _Pragma("unroll")                                                      \
        for (int _t = 0; _t < 4; _t++) {                                       \
            uint2 bh = *(const uint2*)(bp + _t * 64);                          \
            MMA_F16_NEW(dd[_t], ah, bh.x, bh.y);                               \
        }                                                                      \
        _Pragma("unroll")                                                      \
        for (int _t = 0; _t < 4; _t++) {                                       \
            uint2 bl = *(const uint2*)(bp + _t * 64 + 512);                    \
            MMA_F16_ACC(c1[_t], ah, bl.x, bl.y);                               \
        }                                                                      \
        _Pragma("unroll")                                                      \
        for (int _t = 0; _t < 4; _t++) {                                       \
            uint2 bh = *(const uint2*)(bp + _t * 64);                          \
            MMA_F16_ACC(c1[_t], al, bh.x, bh.y);                               \
        }                                                                      \
        _Pragma("unroll")                                                      \
        for (int _t = 0; _t < 4; _t++) {                                       \
            c0[_t][0] += dd[_t][0]; c0[_t][1] += dd[_t][1];                    \
            c0[_t][2] += dd[_t][2]; c0[_t][3] += dd[_t][3];                    \
        }                                                                      \
    }                                                                          \
} while (0)

    float aCur[16], aNxt[16];
    LDA(0, aCur);
#pragma unroll 1
    for (int cc = 0; cc < NCHUNK; cc += 2) {
        CHUNK_BODY(cc, aCur, aNxt);
        CHUNK_BODY(cc + 1, aNxt, aCur);
    }

    {
        int rA = rowgrp * 16 + r0;
#pragma unroll
        for (int t = 0; t < 4; t++) {
            int cb = (eg * 4 + t) * 8 + 2 * quad;
#pragma unroll
            for (int i = 0; i < 4; i++) {
                float v = fmaf(c1[t][i], I11, c0[t][i]);
                int rr = rA + (i >> 1) * 8;
                U[rr * 65 + cb + (i & 1)] = v;
            }
        }
    }
    __syncthreads();

    // ---- epilogue: warps 0..3 (one per SMSP), lanes 0..15, 16 rows/warp ----
    if (wid < 4 && lane < 16) {
        const int r = wid * 16 + lane;
        float L[64];
#pragma unroll
        for (int e = 0; e < 64; e++) L[e] = U[r * 65 + e];

        float m = -INFINITY;
#pragma unroll
        for (int e = 0; e < 64; e++) m = fmaxf(m, L[e]);
        float s = 0.f;
#pragma unroll
        for (int e = 0; e < 64; e++) s += __expf(L[e] - m);
        float sinv = 1.f / s;

        float ws[4];
#pragma unroll
        for (int e = 0; e < 64; e++) {
            float v = __expf(L[e] - m) * sinv;
            v += __shfl_xor_sync(0xffffu, v, 8);
            v += __shfl_xor_sync(0xffffu, v, 4);
            v += __shfl_xor_sync(0xffffu, v, 2);
            v += __shfl_xor_sync(0xffffu, v, 1);
            if ((e & 15) == lane) ws[e >> 4] = v;
        }
#pragma unroll
        for (int q = 0; q < 4; q++) wsum[wid][q * 16 + lane] = ws[q];

        const float4* np = (const float4*)(noise + (size_t)(base + r) * NEXP);
#pragma unroll
        for (int q = 0; q < 16; q++) {
            float4 nv = np[q];
            L[q * 4 + 0] = fmaf(nv.x, nw_s[q * 4 + 0], L[q * 4 + 0]);
            L[q * 4 + 1] = fmaf(nv.y, nw_s[q * 4 + 1], L[q * 4 + 1]);
            L[q * 4 + 2] = fmaf(nv.z, nw_s[q * 4 + 2], L[q * 4 + 2]);
            L[q * 4 + 3] = fmaf(nv.w, nw_s[q * 4 + 3], L[q * 4 + 3]);
        }

        float best[KSEL];
        int bid[KSEL];
        unsigned long long used = 0ull;
#pragma unroll
        for (int k = 0; k < KSEL; k++) {
            float mv = -INFINITY;
            int mi = 0;
#pragma unroll
            for (int e = 0; e < 64; e++) {
                bool ok = !((used >> e) & 1ull);
                if (ok && L[e] > mv) { mv = L[e]; mi = e; }
            }
            used |= 1ull << mi;
            best[k] = mv;
            bid[k] = mi;
        }
        float m0 = best[0];
        float ss = 0.f;
#pragma unroll
        for (int k = 0; k < KSEL; k++) ss += __expf(best[k] - m0);
        float inv = 1.f / ss;

        float4 z = {0.f, 0.f, 0.f, 0.f};
        float4* ow = (float4*)(out_w + (size_t)(base + r) * NEXP);
#pragma unroll
        for (int q = 0; q < 16; q++) ow[q] = z;
#pragma unroll
        for (int k = 0; k < KSEL; k++) {
            out_w[(size_t)(base + r) * NEXP + bid[k]] = __expf(best[k] - m0) * inv;
            out_ids[(size_t)(base + r) * KSEL + k] = (float)bid[k];
        }
    }
    __syncthreads();
    if (tid < NEXP)
        g_part[blockIdx.x * NEXP + tid] =
            wsum[0][tid] + wsum[1][tid] + wsum[2][tid] + wsum[3][tid];

    // ---- fused loss: last CTA reduces g_part (order-fixed -> deterministic) ----
    __threadfence();
    if (tid == 0)
        isLast = (atomicAdd(&g_done, 1u) == (unsigned)(gridDim.x - 1)) ? 1u : 0u;
    __syncthreads();
    if (isLast) {
        if (tid == 0) g_done = 0;   // reset for next graph replay
        const int e = tid & 63, g = tid >> 6;   // 4 partials per expert
        double s = 0.0;
        for (int b = g; b < NBLK; b += 4) s += (double)g_part[b * NEXP + e];
        red[tid] = s;
        __syncthreads();
        if (tid < 64) {
            double v = red[e] + red[64 + e] + red[128 + e] + red[192 + e];
            double d = v / (double)N - 1.0 / 64.0;
            red[tid] = d * d;
        }
        __syncthreads();
        for (int off = 32; off >= 1; off >>= 1) {
            if (tid < off) red[tid] += red[tid + off];
            __syncthreads();
        }
        if (tid == 0) *out_loss = (float)(red[0] / 64.0 * 0.01);
    }
}

extern "C" void kernel_launch(void* const* d_in, const int* in_sizes, int n_in,
                              void* d_out, int out_size)
{
    const float* x     = (const float*)d_in[0];  // [N, 1024]
    const float* w     = (const float*)d_in[1];  // [64, 1024]
    const float* nw    = (const float*)d_in[2];  // [64]
    const float* noise = (const float*)d_in[3];  // [N, 64]

    int N = in_sizes[3] / NEXP;    // 32768
    int nBlocks = N / MTILE;       // 512

    float* out      = (float*)d_out;
    float* out_w    = out;
    float* out_ids  = out + (size_t)N * NEXP;
    float* out_loss = out + (size_t)N * NEXP + (size_t)N * KSEL;

    wsplit_kernel<<<128, 256>>>(w);
    gate_kernel<<<nBlocks, 256>>>(x, nw, noise, out_w, out_ids, out_loss, N);
}